// round 14
// baseline (speedup 1.0000x reference)
#include <cuda_runtime.h>

#define N_FEAT 512
#define FDIM   768
#define HID    256
#define NPAIRS 130816   // 512*511/2
#define KSPLIT 2
#define KHALF  (FDIM / KSPLIT)   // 384

typedef unsigned long long ull;

__device__ __forceinline__ ull fma2(ull a, ull b, ull c) {
    ull d; asm("fma.rn.f32x2 %0, %1, %2, %3;" : "=l"(d) : "l"(a), "l"(b), "l"(c)); return d;
}
__device__ __forceinline__ ull add2(ull a, ull b) {
    ull d; asm("add.rn.f32x2 %0, %1, %2;" : "=l"(d) : "l"(a), "l"(b)); return d;
}
__device__ __forceinline__ ull pack2(float x, float y) {
    ull r; asm("mov.b64 %0, {%1,%2};" : "=l"(r) : "f"(x), "f"(y)); return r;
}
__device__ __forceinline__ void unpack2(ull v, float& x, float& y) {
    asm("mov.b64 {%0,%1}, %2;" : "=f"(x), "=f"(y) : "l"(v));
}

union F4U2 { float4 f4; ull u2[2]; };

// Scratch: [2][512][512] split-K partials.
// cols 0..255 = A_i partial (b1 folded into slice 0) ; cols 256..511 = B_i partial
__device__ float g_AB[KSPLIT * N_FEAT * 512];

// ---------------------------------------------------------------------------
// Kernel 1: C[512,512] = E[512,768] @ [W1_top | W1_bot] (+ b1 on first 256 cols)
// BM=32, BN=64, BK=16, 128 threads, 4x4 microtile via FFMA2 (packed f32x2),
// split-K x2, A duplicated in smem so (a,a) pairs load with one LDS.64.
// ---------------------------------------------------------------------------
#define BM 32
#define BN 64
#define BK 16
#define NT_K (KHALF / BK)   // 24 tiles per block
#define ES_STRIDE (2 * BM + 2)   // 66 floats = 264B, 8B-divisible

__global__ __launch_bounds__(128) void gemm_kernel(const float* __restrict__ E,
                                                   const float* __restrict__ W1,
                                                   const float* __restrict__ b1) {
    __shared__ __align__(16) float Es2[BK][ES_STRIDE];  // duplicated A
    __shared__ __align__(16) float Ws[BK][BN];

    const int tid  = threadIdx.x;
    const int txx  = tid & 15;         // col group 0..15 -> cols txx*4..+3
    const int tyy  = tid >> 4;         // row group 0..7  -> rows tyy*4..+3
    const int row0 = blockIdx.y * BM;
    const int col0 = blockIdx.x * BN;
    const int kz   = blockIdx.z;
    const int kb   = kz * KHALF;

    const int kkL = tid & 15;
    const int rbL = tid >> 4;

    ull acc01[4] = {0, 0, 0, 0};
    ull acc23[4] = {0, 0, 0, 0};
    float eR[4];
    float wR[8];

    // Prologue: prefetch tile 0 into registers
    #pragma unroll
    for (int p = 0; p < 4; p++)
        eR[p] = E[(row0 + rbL + p * 8) * FDIM + kb + kkL];
    #pragma unroll
    for (int p = 0; p < 8; p++) {
        const int idx = p * 128 + tid;
        const int kk  = idx >> 6;
        const int n   = idx & 63;
        const int c   = col0 + n;
        wR[p] = (c < HID) ? W1[(kb + kk) * HID + c]
                          : W1[(FDIM + kb + kk) * HID + (c - HID)];
    }

    for (int t = 0; t < NT_K; t++) {
        // Commit prefetched regs to smem (A duplicated: [2r]=[2r+1]=v)
        #pragma unroll
        for (int p = 0; p < 4; p++) {
            const int r = rbL + p * 8;
            *(float2*)&Es2[kkL][2 * r] = make_float2(eR[p], eR[p]);
        }
        #pragma unroll
        for (int p = 0; p < 8; p++) {
            const int idx = p * 128 + tid;
            Ws[idx >> 6][idx & 63] = wR[p];
        }
        __syncthreads();

        // Prefetch next tile (LDG latency hidden behind compute)
        if (t < NT_K - 1) {
            const int kn = kb + (t + 1) * BK;
            #pragma unroll
            for (int p = 0; p < 4; p++)
                eR[p] = E[(row0 + rbL + p * 8) * FDIM + kn + kkL];
            #pragma unroll
            for (int p = 0; p < 8; p++) {
                const int idx = p * 128 + tid;
                const int kk  = idx >> 6;
                const int n   = idx & 63;
                const int c   = col0 + n;
                wR[p] = (c < HID) ? W1[(kn + kk) * HID + c]
                                  : W1[(FDIM + kn + kk) * HID + (c - HID)];
            }
        }

        // Compute: 8 FFMA2 per kk (16 MACs)
        #pragma unroll
        for (int kk = 0; kk < BK; kk++) {
            F4U2 b; b.f4 = *(const float4*)&Ws[kk][txx * 4];
            #pragma unroll
            for (int m = 0; m < 4; m++) {
                const ull a2 = *(const ull*)&Es2[kk][2 * (tyy * 4 + m)];
                acc01[m] = fma2(a2, b.u2[0], acc01[m]);
                acc23[m] = fma2(a2, b.u2[1], acc23[m]);
            }
        }
        __syncthreads();
    }

    // Epilogue: fold b1 into slice 0 only
    const int cbase = col0 + txx * 4;
    float bias[4];
    #pragma unroll
    for (int n = 0; n < 4; n++) {
        const int c = cbase + n;
        bias[n] = (kz == 0 && c < HID) ? b1[c] : 0.0f;
    }
    float* dst = g_AB + kz * (N_FEAT * 512);
    #pragma unroll
    for (int m = 0; m < 4; m++) {
        const int r = row0 + tyy * 4 + m;
        float o0, o1, o2, o3;
        unpack2(acc01[m], o0, o1);
        unpack2(acc23[m], o2, o3);
        float4 v;
        v.x = o0 + bias[0];
        v.y = o1 + bias[1];
        v.z = o2 + bias[2];
        v.w = o3 + bias[3];
        *(float4*)&dst[r * 512 + cbase] = v;
    }
}

// ---------------------------------------------------------------------------
// Kernel 2: scores. 136 triangular 32x32 tiles (ti<=tj), one block each,
// 256 threads (best measured shape). lane = local j, warp w -> rows w*4..+3.
// Packed f32x2 add/fma; relu on unpacked halves. Staging sums split-K partials.
// sB rows padded to 260 floats: stride % 32 == 4 -> conflict-free.
// ---------------------------------------------------------------------------
#define SB_STRIDE 260
#define NTILES 16          // 512/32
#define NTRI   136         // 16*17/2
#define KOFF   (N_FEAT * 512)

__global__ __launch_bounds__(256) void pair_kernel(const float* __restrict__ W2,
                                                   const float* __restrict__ B2,
                                                   float* __restrict__ out,
                                                   int write_idx) {
    // linear blockIdx.x -> (ti, tj) with ti <= tj
    const int b = blockIdx.x;
    int ti = 0, rem = b;
    #pragma unroll 1
    while (rem >= NTILES - ti) { rem -= NTILES - ti; ti++; }
    const int tj = ti + rem;

    extern __shared__ float sm[];
    float* sA  = sm;                          // 32 rows * 256
    float* sB  = sm + 32 * 256;               // 32 rows * 260 (padded)
    float* sW2 = sB + 32 * SB_STRIDE;         // 256

    const int tid = threadIdx.x;

    if (tid < 64)
        *(float4*)&sW2[tid * 4] = *(const float4*)&W2[tid * 4];

    // Stage A and B tiles (sum the two split-K partials)
    #pragma unroll
    for (int p = 0; p < 8; p++) {
        const int idx = p * 256 + tid;   // float4 index, 2048 total
        const int r   = idx >> 6;
        const int c4  = idx & 63;
        const int offA = (ti * 32 + r) * 512 + c4 * 4;
        const float4 a0 = *(const float4*)&g_AB[offA];
        const float4 a1 = *(const float4*)&g_AB[KOFF + offA];
        float4 va; va.x = a0.x + a1.x; va.y = a0.y + a1.y;
                   va.z = a0.z + a1.z; va.w = a0.w + a1.w;
        *(float4*)&sA[r * 256 + c4 * 4] = va;
        const int offB = (tj * 32 + r) * 512 + 256 + c4 * 4;
        const float4 b0 = *(const float4*)&g_AB[offB];
        const float4 b1v = *(const float4*)&g_AB[KOFF + offB];
        float4 vb; vb.x = b0.x + b1v.x; vb.y = b0.y + b1v.y;
                   vb.z = b0.z + b1v.z; vb.w = b0.w + b1v.w;
        *(float4*)&sB[r * SB_STRIDE + c4 * 4] = vb;
    }
    __syncthreads();

    const int w    = tid >> 5;      // warp 0..7
    const int lane = tid & 31;      // local j
    const float b2v = B2[0];

    ull acc2[4] = {0, 0, 0, 0};     // packed partial sums per row
    const float* bRow  = &sB[lane * SB_STRIDE];
    const float* aBase = &sA[(w * 4) * 256];

    #pragma unroll 4
    for (int c4 = 0; c4 < 64; c4++) {
        F4U2 bv; bv.f4 = *(const float4*)&bRow[c4 * 4];
        F4U2 wv; wv.f4 = *(const float4*)&sW2[c4 * 4];
        #pragma unroll
        for (int s = 0; s < 4; s++) {
            F4U2 av; av.f4 = *(const float4*)&aBase[s * 256 + c4 * 4];
            ull h01 = add2(av.u2[0], bv.u2[0]);
            ull h23 = add2(av.u2[1], bv.u2[1]);
            float f0, f1, f2, f3;
            unpack2(h01, f0, f1);
            unpack2(h23, f2, f3);
            f0 = fmaxf(f0, 0.f); f1 = fmaxf(f1, 0.f);
            f2 = fmaxf(f2, 0.f); f3 = fmaxf(f3, 0.f);
            h01 = pack2(f0, f1);
            h23 = pack2(f2, f3);
            acc2[s] = fma2(h01, wv.u2[0], acc2[s]);
            acc2[s] = fma2(h23, wv.u2[1], acc2[s]);
        }
    }

    const int j = tj * 32 + lane;
    #pragma unroll
    for (int s = 0; s < 4; s++) {
        const int li = w * 4 + s;
        const int i  = ti * 32 + li;
        if (ti != tj || lane > li) {
            float lo, hi;
            unpack2(acc2[s], lo, hi);
            // row-major (i<j) enumeration index, matches jnp.triu_indices(n, k=1)
            const int p = i * N_FEAT - (i * (i + 1)) / 2 + (j - i - 1);
            const float sc = lo + hi + b2v;
            if (write_idx) {
                out[p]              = (float)i;
                out[NPAIRS + p]     = (float)j;
                out[2 * NPAIRS + p] = sc;
            } else {
                out[p] = sc;
            }
        }
    }
}

// ---------------------------------------------------------------------------

extern "C" void kernel_launch(void* const* d_in, const int* in_sizes, int n_in,
                              void* d_out, int out_size) {
    const float* E  = (const float*)d_in[0];
    const float* W1 = (const float*)d_in[1];
    const float* b1 = (const float*)d_in[2];
    const float* W2 = (const float*)d_in[3];
    const float* b2 = (const float*)d_in[4];
    float* out = (float*)d_out;

    dim3 ggrid(512 / BN, 512 / BM, KSPLIT);   // (8,16,2) = 256 blocks
    gemm_kernel<<<ggrid, 128>>>(E, W1, b1);

    const int write_idx = (out_size >= 3 * NPAIRS) ? 1 : 0;
    const size_t smem = (size_t)(32 * 256 + 32 * SB_STRIDE + 256) * sizeof(float); // 67072 B
    cudaFuncSetAttribute(pair_kernel, cudaFuncAttributeMaxDynamicSharedMemorySize, (int)smem);
    pair_kernel<<<NTRI, 256, smem>>>(W2, b2, out, write_idx);
}

// round 16
// speedup vs baseline: 1.0580x; 1.0580x over previous
#include <cuda_runtime.h>

#define N_FEAT 512
#define FDIM   768
#define HID    256
#define NPAIRS 130816   // 512*511/2
#define KSPLIT 4
#define KQ     (FDIM / KSPLIT)   // 192

// Scratch: [4][512][512] split-K partials.
// cols 0..255 = A_i partial (b1 folded into slice 0) ; cols 256..511 = B_i partial
__device__ float g_AB[KSPLIT * N_FEAT * 512];

// ---------------------------------------------------------------------------
// Kernel 1: C[512,512] = E[512,768] @ [W1_top | W1_bot] (+ b1 on first 256 cols)
// BM=32, BN=64, BK=16, 128 threads, 4x4 microtile, split-K x4
// grid (8,16,4) = 512 blocks -> ~3.5 blocks/SM (14 warps), LDG reg-prefetched.
// ---------------------------------------------------------------------------
#define BM 32
#define BN 64
#define BK 16
#define NT_K (KQ / BK)   // 12 tiles per block

__global__ __launch_bounds__(128) void gemm_kernel(const float* __restrict__ E,
                                                   const float* __restrict__ W1,
                                                   const float* __restrict__ b1) {
    __shared__ float Es[BK][BM + 4];   // [16][36]
    __shared__ float Ws[BK][BN];       // [16][64]

    const int tid  = threadIdx.x;
    const int txx  = tid & 15;         // col group 0..15 -> cols txx*4..+3
    const int tyy  = tid >> 4;         // row group 0..7  -> rows tyy*4..+3
    const int row0 = blockIdx.y * BM;
    const int col0 = blockIdx.x * BN;
    const int kz   = blockIdx.z;
    const int kb   = kz * KQ;

    const int kkL = tid & 15;
    const int rbL = tid >> 4;

    float acc[4][4] = {};
    float eR[4];
    float wR[8];

    // Prologue: prefetch tile 0 into registers
    #pragma unroll
    for (int p = 0; p < 4; p++)
        eR[p] = E[(row0 + rbL + p * 8) * FDIM + kb + kkL];
    #pragma unroll
    for (int p = 0; p < 8; p++) {
        const int idx = p * 128 + tid;
        const int kk  = idx >> 6;
        const int n   = idx & 63;
        const int c   = col0 + n;
        wR[p] = (c < HID) ? W1[(kb + kk) * HID + c]
                          : W1[(FDIM + kb + kk) * HID + (c - HID)];
    }

    for (int t = 0; t < NT_K; t++) {
        // Commit prefetched regs to smem
        #pragma unroll
        for (int p = 0; p < 4; p++)
            Es[kkL][rbL + p * 8] = eR[p];
        #pragma unroll
        for (int p = 0; p < 8; p++) {
            const int idx = p * 128 + tid;
            Ws[idx >> 6][idx & 63] = wR[p];
        }
        __syncthreads();

        // Prefetch next tile (LDG latency hidden behind compute below)
        if (t < NT_K - 1) {
            const int kn = kb + (t + 1) * BK;
            #pragma unroll
            for (int p = 0; p < 4; p++)
                eR[p] = E[(row0 + rbL + p * 8) * FDIM + kn + kkL];
            #pragma unroll
            for (int p = 0; p < 8; p++) {
                const int idx = p * 128 + tid;
                const int kk  = idx >> 6;
                const int n   = idx & 63;
                const int c   = col0 + n;
                wR[p] = (c < HID) ? W1[(kn + kk) * HID + c]
                                  : W1[(FDIM + kn + kk) * HID + (c - HID)];
            }
        }

        // Compute
        #pragma unroll
        for (int kk = 0; kk < BK; kk++) {
            const float4 a = *(const float4*)&Es[kk][tyy * 4];
            const float4 b = *(const float4*)&Ws[kk][txx * 4];
            const float av[4] = {a.x, a.y, a.z, a.w};
            const float bv[4] = {b.x, b.y, b.z, b.w};
            #pragma unroll
            for (int m = 0; m < 4; m++)
                #pragma unroll
                for (int n = 0; n < 4; n++)
                    acc[m][n] = fmaf(av[m], bv[n], acc[m][n]);
        }
        __syncthreads();
    }

    // Epilogue: fold b1 into slice 0 only
    const int cbase = col0 + txx * 4;
    float bias[4];
    #pragma unroll
    for (int n = 0; n < 4; n++) {
        const int c = cbase + n;
        bias[n] = (kz == 0 && c < HID) ? b1[c] : 0.0f;
    }
    float* dst = g_AB + kz * (N_FEAT * 512);
    #pragma unroll
    for (int m = 0; m < 4; m++) {
        const int r = row0 + tyy * 4 + m;
        float4 v;
        v.x = acc[m][0] + bias[0];
        v.y = acc[m][1] + bias[1];
        v.z = acc[m][2] + bias[2];
        v.w = acc[m][3] + bias[3];
        *(float4*)&dst[r * 512 + cbase] = v;
    }
}

// ---------------------------------------------------------------------------
// Kernel 2: scores. 136 triangular 32x32 tiles (ti<=tj), one block each,
// 256 threads (measured-best shape, scalar math). lane = local j, warp w ->
// rows w*4..+3. Staging sums 4 split-K partials. sB stride 260 = conflict-free.
// ---------------------------------------------------------------------------
#define SB_STRIDE 260
#define NTILES 16          // 512/32
#define NTRI   136         // 16*17/2
#define KOFF   (N_FEAT * 512)

__global__ __launch_bounds__(256) void pair_kernel(const float* __restrict__ W2,
                                                   const float* __restrict__ B2,
                                                   float* __restrict__ out,
                                                   int write_idx) {
    // linear blockIdx.x -> (ti, tj) with ti <= tj
    const int b = blockIdx.x;
    int ti = 0, rem = b;
    #pragma unroll 1
    while (rem >= NTILES - ti) { rem -= NTILES - ti; ti++; }
    const int tj = ti + rem;

    extern __shared__ float sm[];
    float* sA  = sm;                          // 32 rows * 256
    float* sB  = sm + 32 * 256;               // 32 rows * 260 (padded)
    float* sW2 = sB + 32 * SB_STRIDE;         // 256

    const int tid = threadIdx.x;

    if (tid < 64)
        *(float4*)&sW2[tid * 4] = *(const float4*)&W2[tid * 4];

    // Stage A and B tiles (sum the four split-K partials)
    #pragma unroll
    for (int p = 0; p < 8; p++) {
        const int idx = p * 256 + tid;   // float4 index, 2048 total
        const int r   = idx >> 6;
        const int c4  = idx & 63;
        const int offA = (ti * 32 + r) * 512 + c4 * 4;
        float4 va = *(const float4*)&g_AB[offA];
        #pragma unroll
        for (int k = 1; k < KSPLIT; k++) {
            const float4 t = *(const float4*)&g_AB[k * KOFF + offA];
            va.x += t.x; va.y += t.y; va.z += t.z; va.w += t.w;
        }
        *(float4*)&sA[r * 256 + c4 * 4] = va;

        const int offB = (tj * 32 + r) * 512 + 256 + c4 * 4;
        float4 vb = *(const float4*)&g_AB[offB];
        #pragma unroll
        for (int k = 1; k < KSPLIT; k++) {
            const float4 t = *(const float4*)&g_AB[k * KOFF + offB];
            vb.x += t.x; vb.y += t.y; vb.z += t.z; vb.w += t.w;
        }
        *(float4*)&sB[r * SB_STRIDE + c4 * 4] = vb;
    }
    __syncthreads();

    const int w    = tid >> 5;      // warp 0..7
    const int lane = tid & 31;      // local j
    const float b2v = B2[0];

    float acc[4] = {0.f, 0.f, 0.f, 0.f};
    const float* bRow  = &sB[lane * SB_STRIDE];
    const float* aBase = &sA[(w * 4) * 256];

    #pragma unroll 4
    for (int c4 = 0; c4 < 64; c4++) {
        const float4 bv = *(const float4*)&bRow[c4 * 4];
        const float4 wv = *(const float4*)&sW2[c4 * 4];
        #pragma unroll
        for (int s = 0; s < 4; s++) {
            const float4 a = *(const float4*)&aBase[s * 256 + c4 * 4];
            float h;
            h = fmaxf(a.x + bv.x, 0.f); acc[s] = fmaf(h, wv.x, acc[s]);
            h = fmaxf(a.y + bv.y, 0.f); acc[s] = fmaf(h, wv.y, acc[s]);
            h = fmaxf(a.z + bv.z, 0.f); acc[s] = fmaf(h, wv.z, acc[s]);
            h = fmaxf(a.w + bv.w, 0.f); acc[s] = fmaf(h, wv.w, acc[s]);
        }
    }

    const int j = tj * 32 + lane;
    #pragma unroll
    for (int s = 0; s < 4; s++) {
        const int li = w * 4 + s;
        const int i  = ti * 32 + li;
        if (ti != tj || lane > li) {
            // row-major (i<j) enumeration index, matches jnp.triu_indices(n, k=1)
            const int p = i * N_FEAT - (i * (i + 1)) / 2 + (j - i - 1);
            const float sc = acc[s] + b2v;
            if (write_idx) {
                out[p]              = (float)i;
                out[NPAIRS + p]     = (float)j;
                out[2 * NPAIRS + p] = sc;
            } else {
                out[p] = sc;
            }
        }
    }
}

// ---------------------------------------------------------------------------

extern "C" void kernel_launch(void* const* d_in, const int* in_sizes, int n_in,
                              void* d_out, int out_size) {
    const float* E  = (const float*)d_in[0];
    const float* W1 = (const float*)d_in[1];
    const float* b1 = (const float*)d_in[2];
    const float* W2 = (const float*)d_in[3];
    const float* b2 = (const float*)d_in[4];
    float* out = (float*)d_out;

    dim3 ggrid(512 / BN, 512 / BM, KSPLIT);   // (8,16,4) = 512 blocks
    gemm_kernel<<<ggrid, 128>>>(E, W1, b1);

    const int write_idx = (out_size >= 3 * NPAIRS) ? 1 : 0;
    const size_t smem = (size_t)(32 * 256 + 32 * SB_STRIDE + 256) * sizeof(float); // 67072 B
    cudaFuncSetAttribute(pair_kernel, cudaFuncAttributeMaxDynamicSharedMemorySize, (int)smem);
    pair_kernel<<<NTRI, 256, smem>>>(W2, b2, out, write_idx);
}